// round 4
// baseline (speedup 1.0000x reference)
#include <cuda_runtime.h>

#define NPTS     200000
#define NREL     128
#define SCT_PTS  2048
#define NBLK_MAX ((NPTS + SCT_PTS - 1) / SCT_PTS)   // 98
#define CELLCAP  64        // per-(relation, block) capacity; mean 16, sd 4
#define CHUNKS   13        // CTAs per relation in k_main
#define WPC      4         // warps per CTA

// ---- device scratch (no allocations; every word below is fully
//      overwritten each launch by its owning scatter block => no reset) ----
__device__ int g_cellcnt[NREL * NBLK_MAX];
__device__ int g_pids[NREL * NBLK_MAX * CELLCAP];

// Scatter: block blk bins its 2048 points into its OWN fixed region per
// relation: g_pids[(r*NBLK_MAX + blk)*CELLCAP + local]. Counts are plain
// stores (no global atomics, no reset kernel). Overflow beyond CELLCAP
// (>=12 sigma, statistically unreachable) is computed inline.
__global__ void __launch_bounds__(256)
k_scatter(const int* __restrict__ rel, int n,
          const float* __restrict__ x,
          const float* __restrict__ w,
          float* __restrict__ out) {
    __shared__ int s_rel[SCT_PTS];
    __shared__ int s_hist[NREL];
    __shared__ int s_cur[NREL];

    int blk = blockIdx.x;
    int start = blk * SCT_PTS;
    int cnt = n - start;
    if (cnt > SCT_PTS) cnt = SCT_PTS;
    if (cnt <= 0) {
        for (int i = threadIdx.x; i < NREL; i += blockDim.x)
            g_cellcnt[i * NBLK_MAX + blk] = 0;
        return;
    }

    for (int i = threadIdx.x; i < NREL; i += blockDim.x) {
        s_hist[i] = 0;
        s_cur[i]  = 0;
    }
    __syncthreads();

    for (int i = threadIdx.x; i < cnt; i += blockDim.x) {
        int r = __ldg(rel + start + i);
        s_rel[i] = r;
        atomicAdd(&s_hist[r], 1);
    }
    __syncthreads();

    for (int i = threadIdx.x; i < NREL; i += blockDim.x) {
        int c = s_hist[i];
        g_cellcnt[i * NBLK_MAX + blk] = (c > CELLCAP) ? CELLCAP : c;
    }
    __syncthreads();

    for (int i = threadIdx.x; i < cnt; i += blockDim.x) {
        int r = s_rel[i];
        int pos = atomicAdd(&s_cur[r], 1);
        int p = start + i;
        if (pos < CELLCAP) {
            g_pids[(r * NBLK_MAX + blk) * CELLCAP + pos] = p;
        } else {
            // Dead-in-practice overflow: compute this point directly.
            const float* xr = x + (size_t)p * 128;
            float* orow = out + (size_t)p * 128;
            for (int bb = 0; bb < 16; bb++) {
                const float* wb = w + (size_t)((r * 16 + bb) * 8) * 8;
                for (int o = 0; o < 8; o++) {
                    float acc = 0.f;
                    for (int ii = 0; ii < 8; ii++)
                        acc = fmaf(xr[bb * 8 + ii], wb[ii * 8 + o], acc);
                    orow[bb * 8 + o] = acc;
                }
            }
        }
    }
}

// Main: CTA = (relation r, chunk). lane = 2*b + h owns block b, out-half h;
// its 32 weight floats live in registers for the whole CTA. Each warp walks
// whole cells of its relation; per 4 points: 4 independent shfls + 8
// independent LDG.128 in flight + 4 coalesced 512B stores.
__global__ void __launch_bounds__(32 * WPC)
k_main(const float4* __restrict__ x4,
       const float4* __restrict__ w4,
       float4* __restrict__ out4,
       int nblk) {
    int r     = blockIdx.x / CHUNKS;
    int chunk = blockIdx.x % CHUNKS;
    int lane  = threadIdx.x & 31;
    int wrp   = threadIdx.x >> 5;
    int b     = lane >> 1;
    int h     = lane & 1;

    const float4* wp = w4 + (size_t)((r * 16 + b) * 8) * 2 + h;
    float4 wt[8];
#pragma unroll
    for (int i = 0; i < 8; i++) wt[i] = __ldg(wp + 2 * i);

    const int nwarp = CHUNKS * WPC;            // 52 warps per relation
    for (int cell = chunk * WPC + wrp; cell < nblk; cell += nwarp) {
        int cidx = r * NBLK_MAX + cell;
        int cnt = __ldg(&g_cellcnt[cidx]);
        const int* pids = g_pids + (size_t)cidx * CELLCAP;

        int pidA = (lane < cnt)      ? __ldg(pids + lane)      : 0;
        int pidB = (32 + lane < cnt) ? __ldg(pids + 32 + lane) : 0;

        int k = 0;
        for (; k + 4 <= cnt; k += 4) {
            int src = (k < 32) ? pidA : pidB;
            int kk = k & 31;
            int p0 = __shfl_sync(0xffffffffu, src, kk);
            int p1 = __shfl_sync(0xffffffffu, src, kk + 1);
            int p2 = __shfl_sync(0xffffffffu, src, kk + 2);
            int p3 = __shfl_sync(0xffffffffu, src, kk + 3);

            float4 xa0 = __ldg(x4 + (size_t)p0 * 32 + 2 * b);
            float4 xb0 = __ldg(x4 + (size_t)p0 * 32 + 2 * b + 1);
            float4 xa1 = __ldg(x4 + (size_t)p1 * 32 + 2 * b);
            float4 xb1 = __ldg(x4 + (size_t)p1 * 32 + 2 * b + 1);
            float4 xa2 = __ldg(x4 + (size_t)p2 * 32 + 2 * b);
            float4 xb2 = __ldg(x4 + (size_t)p2 * 32 + 2 * b + 1);
            float4 xa3 = __ldg(x4 + (size_t)p3 * 32 + 2 * b);
            float4 xb3 = __ldg(x4 + (size_t)p3 * 32 + 2 * b + 1);

#define DO_POINT(P, XA, XB)                                                  \
            {                                                                \
                float xs[8] = {XA.x, XA.y, XA.z, XA.w,                       \
                               XB.x, XB.y, XB.z, XB.w};                      \
                float a0 = 0.f, a1 = 0.f, a2 = 0.f, a3 = 0.f;                \
                _Pragma("unroll")                                            \
                for (int i = 0; i < 8; i++) {                                \
                    a0 = fmaf(xs[i], wt[i].x, a0);                           \
                    a1 = fmaf(xs[i], wt[i].y, a1);                           \
                    a2 = fmaf(xs[i], wt[i].z, a2);                           \
                    a3 = fmaf(xs[i], wt[i].w, a3);                           \
                }                                                            \
                out4[(size_t)(P) * 32 + lane] = make_float4(a0, a1, a2, a3); \
            }

            DO_POINT(p0, xa0, xb0)
            DO_POINT(p1, xa1, xb1)
            DO_POINT(p2, xa2, xb2)
            DO_POINT(p3, xa3, xb3)
        }
        for (; k < cnt; k++) {
            int src = (k < 32) ? pidA : pidB;
            int p = __shfl_sync(0xffffffffu, src, k & 31);
            float4 xa = __ldg(x4 + (size_t)p * 32 + 2 * b);
            float4 xb = __ldg(x4 + (size_t)p * 32 + 2 * b + 1);
            DO_POINT(p, xa, xb)
        }
#undef DO_POINT
    }
}

extern "C" void kernel_launch(void* const* d_in, const int* in_sizes, int n_in,
                              void* d_out, int out_size) {
    const float* x      = (const float*)d_in[0];   // [NPTS, 128] f32
    const float* blocks = (const float*)d_in[1];   // [128,16,8,8] f32
    const int*   rel    = (const int*)d_in[2];     // [NPTS] i32
    int n = in_sizes[2];
    if (n > NPTS) n = NPTS;  // scratch bound

    int nblk = (n + SCT_PTS - 1) / SCT_PTS;        // 98
    k_scatter<<<nblk, 256>>>(rel, n, x, blocks, (float*)d_out);
    k_main<<<NREL * CHUNKS, 32 * WPC>>>(
        (const float4*)x, (const float4*)blocks, (float4*)d_out, nblk);
}

// round 5
// speedup vs baseline: 1.2306x; 1.2306x over previous
#include <cuda_runtime.h>

#define NPTS     200000
#define NREL     128
#define SCT_PTS  1024
#define NBLK     ((NPTS + SCT_PTS - 1) / SCT_PTS)   // 196
#define CELLCAP  32        // per-(relation, block) capacity; mean 8, sd 2.8
#define GRID_MAIN (152 * 8)  // one full wave at 8 CTAs/SM
#define WPC      4

// ---- device scratch (no allocations). g_cellcnt / g_cursor are fully
//      rewritten by k_scatter every launch; g_pids slots beyond a cell's
//      count are never consumed => no reset kernel needed. ----
__device__ int g_cellcnt[NREL * NBLK];
__device__ int g_cursor[NREL];
__device__ int g_pids[NREL * NBLK * CELLCAP];

// Scatter: block blk bins its 1024 points into its OWN fixed cell per
// relation: g_pids[(r*NBLK + blk)*CELLCAP + local]. Counts are plain
// stores (no global atomics). Block 0 also rezeroes the work-stealing
// cursors for k_main. Overflow beyond CELLCAP (>8 sigma) computed inline.
__global__ void __launch_bounds__(256)
k_scatter(const int* __restrict__ rel, int n,
          const float* __restrict__ x,
          const float* __restrict__ w,
          float* __restrict__ out) {
    __shared__ int s_rel[SCT_PTS];
    __shared__ int s_hist[NREL];
    __shared__ int s_cur[NREL];

    int blk = blockIdx.x;
    if (blk == 0) {
        for (int i = threadIdx.x; i < NREL; i += blockDim.x) g_cursor[i] = 0;
    }

    int start = blk * SCT_PTS;
    int cnt = n - start;
    if (cnt > SCT_PTS) cnt = SCT_PTS;

    for (int i = threadIdx.x; i < NREL; i += blockDim.x) {
        s_hist[i] = 0;
        s_cur[i]  = 0;
    }
    __syncthreads();

    for (int i = threadIdx.x; i < cnt; i += blockDim.x) {
        int r = __ldg(rel + start + i);
        s_rel[i] = r;
        atomicAdd(&s_hist[r], 1);
    }
    __syncthreads();

    for (int i = threadIdx.x; i < NREL; i += blockDim.x) {
        int c = s_hist[i];
        g_cellcnt[i * NBLK + blk] = (c > CELLCAP) ? CELLCAP : c;
    }
    __syncthreads();

    for (int i = threadIdx.x; i < cnt; i += blockDim.x) {
        int r = s_rel[i];
        int pos = atomicAdd(&s_cur[r], 1);
        int p = start + i;
        if (pos < CELLCAP) {
            g_pids[(r * NBLK + blk) * CELLCAP + pos] = p;
        } else {
            // Dead-in-practice overflow: compute this point directly.
            const float* xr = x + (size_t)p * 128;
            float* orow = out + (size_t)p * 128;
            for (int bb = 0; bb < 16; bb++) {
                const float* wb = w + (size_t)((r * 16 + bb) * 8) * 8;
                for (int o = 0; o < 8; o++) {
                    float acc = 0.f;
                    for (int ii = 0; ii < 8; ii++)
                        acc = fmaf(xr[bb * 8 + ii], wb[ii * 8 + o], acc);
                    orow[bb * 8 + o] = acc;
                }
            }
        }
    }
}

// Main: exactly one wave (1216 CTAs x 4 warps = 4864 warps = 38 per
// relation). Warp -> relation via (global_warp & 127); its 32 weight floats
// live in registers for the whole kernel. Warps of a relation steal cells
// from g_cursor[r] (spread atomics, ~25k total). Next cell's metadata is
// fetched before processing the current cell; pid reads are independent of
// the count (stale lanes never consumed). Per point: 512B coalesced x read
// + 512B coalesced out write, unroll-4 (8 LDG.128 in flight).
__global__ void __launch_bounds__(32 * WPC, 8)
k_main(const float4* __restrict__ x4,
       const float4* __restrict__ w4,
       float4* __restrict__ out4,
       int ncell) {
    int gw   = blockIdx.x * WPC + (threadIdx.x >> 5);
    int r    = gw & (NREL - 1);
    int lane = threadIdx.x & 31;
    int b    = lane >> 1;
    int h    = lane & 1;

    const float4* wp = w4 + (size_t)((r * 16 + b) * 8) * 2 + h;
    float4 wt[8];
#pragma unroll
    for (int i = 0; i < 8; i++) wt[i] = __ldg(wp + 2 * i);

    int zero = (lane == 0) ? 1 : 1;  // (keeps lane alive for atomics path)
    (void)zero;

    int c = 0;
    if (lane == 0) c = atomicAdd(&g_cursor[r], 1);
    c = __shfl_sync(0xffffffffu, c, 0);
    if (c >= ncell) return;

    int cidx  = r * NBLK + c;
    int cnt   = __ldg(&g_cellcnt[cidx]);
    int mypid = __ldg(g_pids + (size_t)cidx * CELLCAP + lane);

    for (;;) {
        // -- prefetch next cell (id, count, pids) before processing --
        int c2 = 0;
        if (lane == 0) c2 = atomicAdd(&g_cursor[r], 1);
        c2 = __shfl_sync(0xffffffffu, c2, 0);
        int cnt2 = 0, mypid2 = 0;
        if (c2 < ncell) {
            int cidx2 = r * NBLK + c2;
            cnt2   = __ldg(&g_cellcnt[cidx2]);
            mypid2 = __ldg(g_pids + (size_t)cidx2 * CELLCAP + lane);
        }

        // -- process current cell --
        int k = 0;
        for (; k + 4 <= cnt; k += 4) {
            int p0 = __shfl_sync(0xffffffffu, mypid, k);
            int p1 = __shfl_sync(0xffffffffu, mypid, k + 1);
            int p2 = __shfl_sync(0xffffffffu, mypid, k + 2);
            int p3 = __shfl_sync(0xffffffffu, mypid, k + 3);

            float4 xa0 = __ldg(x4 + (size_t)p0 * 32 + 2 * b);
            float4 xb0 = __ldg(x4 + (size_t)p0 * 32 + 2 * b + 1);
            float4 xa1 = __ldg(x4 + (size_t)p1 * 32 + 2 * b);
            float4 xb1 = __ldg(x4 + (size_t)p1 * 32 + 2 * b + 1);
            float4 xa2 = __ldg(x4 + (size_t)p2 * 32 + 2 * b);
            float4 xb2 = __ldg(x4 + (size_t)p2 * 32 + 2 * b + 1);
            float4 xa3 = __ldg(x4 + (size_t)p3 * 32 + 2 * b);
            float4 xb3 = __ldg(x4 + (size_t)p3 * 32 + 2 * b + 1);

#define DO_POINT(P, XA, XB)                                                  \
            {                                                                \
                float xs[8] = {XA.x, XA.y, XA.z, XA.w,                       \
                               XB.x, XB.y, XB.z, XB.w};                      \
                float a0 = 0.f, a1 = 0.f, a2 = 0.f, a3 = 0.f;                \
                _Pragma("unroll")                                            \
                for (int i = 0; i < 8; i++) {                                \
                    a0 = fmaf(xs[i], wt[i].x, a0);                           \
                    a1 = fmaf(xs[i], wt[i].y, a1);                           \
                    a2 = fmaf(xs[i], wt[i].z, a2);                           \
                    a3 = fmaf(xs[i], wt[i].w, a3);                           \
                }                                                            \
                out4[(size_t)(P) * 32 + lane] = make_float4(a0, a1, a2, a3); \
            }

            DO_POINT(p0, xa0, xb0)
            DO_POINT(p1, xa1, xb1)
            DO_POINT(p2, xa2, xb2)
            DO_POINT(p3, xa3, xb3)
        }
        for (; k < cnt; k++) {
            int p = __shfl_sync(0xffffffffu, mypid, k);
            float4 xa = __ldg(x4 + (size_t)p * 32 + 2 * b);
            float4 xb = __ldg(x4 + (size_t)p * 32 + 2 * b + 1);
            DO_POINT(p, xa, xb)
        }
#undef DO_POINT

        if (c2 >= ncell) break;
        cnt = cnt2;
        mypid = mypid2;
    }
}

extern "C" void kernel_launch(void* const* d_in, const int* in_sizes, int n_in,
                              void* d_out, int out_size) {
    const float* x      = (const float*)d_in[0];   // [NPTS, 128] f32
    const float* blocks = (const float*)d_in[1];   // [128,16,8,8] f32
    const int*   rel    = (const int*)d_in[2];     // [NPTS] i32
    int n = in_sizes[2];
    if (n > NPTS) n = NPTS;  // scratch bound

    int nblk = (n + SCT_PTS - 1) / SCT_PTS;        // 196
    k_scatter<<<NBLK, 256>>>(rel, n, x, blocks, (float*)d_out);
    k_main<<<GRID_MAIN, 32 * WPC>>>(
        (const float4*)x, (const float4*)blocks, (float4*)d_out, nblk);
}